// round 5
// baseline (speedup 1.0000x reference)
#include <cuda_runtime.h>
#include <math.h>

#define NB   4
#define BSZ  8
#define NF   128
#define WDIM 512
#define IMG  256

typedef unsigned long long ull;

// ---------------- packed f32x2 helpers (Blackwell sm_100a) -------------------
__device__ __forceinline__ ull pk2(float lo, float hi) {
    ull r; asm("mov.b64 %0, {%1, %2};" : "=l"(r) : "f"(lo), "f"(hi)); return r;
}
__device__ __forceinline__ void upk2(ull v, float& lo, float& hi) {
    asm("mov.b64 {%0, %1}, %2;" : "=f"(lo), "=f"(hi) : "l"(v));
}
__device__ __forceinline__ void fma2(ull& d, ull a, ull b) {
    asm("fma.rn.f32x2 %0, %1, %2, %0;" : "+l"(d) : "l"(a), "l"(b));
}

// ---------------- scratch (static device globals; no allocation) -------------
__device__ float g_xa[BSZ * NF * IMG * IMG];
__device__ float g_xb[BSZ * NF * IMG * IMG];
__device__ float g_ws[BSZ * NF * NF * 9];
__device__ float g_s[NB * BSZ * NF];
__device__ float g_rgb[BSZ * (32*32 + 64*64 + 128*128 + 256*256)];

// ---------------- styles -----------------------------------------------------
__global__ void k_style(const float* __restrict__ w, const float* __restrict__ tsw,
                        const float* __restrict__ tsb) {
    int i = blockIdx.x / BSZ, b = blockIdx.x % BSZ;
    int c = threadIdx.x;
    __shared__ float sw[WDIM];
    for (int d = threadIdx.x; d < WDIM; d += blockDim.x)
        sw[d] = w[(i * BSZ + b) * WDIM + d];
    __syncthreads();
    const float* tw = tsw + (i * NF + c) * WDIM;
    float acc = 0.f;
    #pragma unroll 4
    for (int d = 0; d < WDIM; d++) acc += sw[d] * tw[d];
    const float cl = 0.044194173824159216f;   // 1/sqrt(512)
    g_s[(i * BSZ + b) * NF + c] = acc * cl + tsb[i * NF + c];
}

// ---------------- modulated + demodulated weights ----------------------------
__global__ void k_modw(const float* __restrict__ conv_w, int i, int j) {
    int b = blockIdx.x / NF, co = blockIdx.x % NF;
    const float* wsrc = conv_w + (((size_t)(i * 2 + j) * NF + co) * NF) * 9;
    const float* s = g_s + (i * BSZ + b) * NF;
    const float c = 0.029462782549439483f;    // 1/sqrt(128*9)
    __shared__ float buf[NF * 9];
    __shared__ float red[32];
    float ss = 0.f;
    for (int t = threadIdx.x; t < NF * 9; t += blockDim.x) {
        float v = wsrc[t] * c * s[t / 9];
        buf[t] = v;
        ss += v * v;
    }
    for (int o = 16; o; o >>= 1) ss += __shfl_xor_sync(0xffffffffu, ss, o);
    if ((threadIdx.x & 31) == 0) red[threadIdx.x >> 5] = ss;
    __syncthreads();
    if (threadIdx.x < 32) {
        float v = (threadIdx.x < (blockDim.x >> 5)) ? red[threadIdx.x] : 0.f;
        for (int o = 16; o; o >>= 1) v += __shfl_xor_sync(0xffffffffu, v, o);
        if (threadIdx.x == 0) red[0] = v;
    }
    __syncthreads();
    float dem = rsqrtf(red[0] + 1e-8f);
    float* dst = g_ws + ((size_t)(b * NF) + co) * (NF * 9);
    for (int t = threadIdx.x; t < NF * 9; t += blockDim.x) dst[t] = buf[t] * dem;
}

// ---------------- initial constant -------------------------------------------
__global__ void k_init(const float* __restrict__ ic, float* __restrict__ x) {
    int idx = blockIdx.x * blockDim.x + threadIdx.x;
    if (idx >= BSZ * NF * 32 * 32) return;
    int per = NF * 32 * 32;
    float v = ic[idx % per];
    x[idx] = v > 0.f ? v : 0.f;
}

// ---------------- bilinear 2x upsample ---------------------------------------
__global__ void k_up(const float* __restrict__ in, float* __restrict__ out, int rin) {
    int rout = rin * 2;
    int idx = blockIdx.x * blockDim.x + threadIdx.x;
    int total = BSZ * NF * rout * rout;
    if (idx >= total) return;
    int x = idx % rout;
    int t2 = idx / rout;
    int y = t2 % rout;
    int bc = t2 / rout;
    float fy = y * 0.5f - 0.25f, fx = x * 0.5f - 0.25f;
    int iy0 = (int)floorf(fy), ix0 = (int)floorf(fx);
    float ty = fy - iy0, tx = fx - ix0;
    int y0c = max(iy0, 0), y1c = min(iy0 + 1, rin - 1);
    int x0c = max(ix0, 0), x1c = min(ix0 + 1, rin - 1);
    const float* p = in + (size_t)bc * rin * rin;
    float v00 = p[y0c * rin + x0c], v01 = p[y0c * rin + x1c];
    float v10 = p[y1c * rin + x0c], v11 = p[y1c * rin + x1c];
    float v0 = v00 + tx * (v01 - v00);
    float v1 = v10 + tx * (v11 - v10);
    out[idx] = v0 + ty * (v1 - v0);
}

// ---------------- modulated conv3x3, f32x2 with pre-paired smem --------------
// Dynamic smem layout:
//   s_in : [8][TY+2][PW] ull  (pre-paired input, PW = TX+3 for bank stagger)
//   s_w  : [32][8][10]   ull  ({w,w} pairs, 9 used + pad to 16B multiple)
template <int TX, int TY>
__global__ void __launch_bounds__(256)
k_conv(const float* __restrict__ xin, float* __restrict__ xout,
       const float* __restrict__ noise, const float* __restrict__ sn_ptr,
       const float* __restrict__ bias, int r) {
    constexpr int PX = TX / 8;
    constexpr int PY = TY / 8;
    constexpr int NP = PX / 2;
    constexpr int PW = TX + 3;
    constexpr int IN_ULL = 8 * (TY + 2) * PW;

    extern __shared__ ull dyn[];
    ull* s_in = dyn;                       // [8][TY+2][PW]
    ull* s_w  = dyn + IN_ULL;              // [32][8][10]

    int bz = blockIdx.z;
    int b = bz >> 2, cg = bz & 3;
    int x0 = blockIdx.x * TX, y0 = blockIdx.y * TY;
    int t = threadIdx.x;
    int co_sub = t >> 6, pix = t & 63;
    int lx = (pix & 7) * PX, ly = (pix >> 3) * PY;
    int co0 = cg * 32;

    ull acc2[8][PY][NP];
    #pragma unroll
    for (int a = 0; a < 8; a++)
        #pragma unroll
        for (int yy = 0; yy < PY; yy++)
            #pragma unroll
            for (int xp = 0; xp < NP; xp++) acc2[a][yy][xp] = 0ull;

    const size_t ws_b = (size_t)b * NF * (NF * 9);

    for (int c0 = 0; c0 < NF; c0 += 8) {
        // ---- weights: 32co x 8ci x 9, pre-packed {w,w}, padded stride 10
        {
            int co_l = t >> 3, ci_l = t & 7;
            const float* src = g_ws + ws_b + ((size_t)(co0 + co_l) * NF + (c0 + ci_l)) * 9;
            ull* dst = s_w + (co_l * 8 + ci_l) * 10;
            #pragma unroll
            for (int k = 0; k < 9; k++) { float w = src[k]; dst[k] = pk2(w, w); }
        }
        // ---- pre-paired input tile: 8ci x (TY+2) x (TX+1) pairs, zero padded
        for (int e = t; e < 8 * (TY + 2) * (TX + 1); e += 256) {
            int ci_l = e / ((TY + 2) * (TX + 1));
            int rem = e - ci_l * ((TY + 2) * (TX + 1));
            int sy = rem / (TX + 1), sx = rem - sy * (TX + 1);
            int gy = y0 + sy - 1, gxa = x0 + sx - 1;
            float v0 = 0.f, v1 = 0.f;
            if (gy >= 0 && gy < r) {
                const float* row = xin + (((size_t)(b * NF + c0 + ci_l)) * r + gy) * r;
                if (gxa >= 0 && gxa < r) v0 = row[gxa];
                if (gxa + 1 < r)          v1 = row[gxa + 1];
            }
            s_in[(ci_l * (TY + 2) + sy) * PW + sx] = pk2(v0, v1);
        }
        __syncthreads();

        #pragma unroll
        for (int ci = 0; ci < 8; ci++) {
            ull inp[PY + 2][PX + 1];
            #pragma unroll
            for (int row = 0; row < PY + 2; row++)
                #pragma unroll
                for (int d = 0; d < PX + 1; d++)
                    inp[row][d] = s_in[(ci * (TY + 2) + ly + row) * PW + lx + d];
            #pragma unroll
            for (int cl = 0; cl < 8; cl++) {
                const ull* wbase = s_w + ((co_sub * 8 + cl) * 8 + ci) * 10;
                const ulong2* wp2 = reinterpret_cast<const ulong2*>(wbase);
                ulong2 q0 = wp2[0], q1 = wp2[1], q2 = wp2[2], q3 = wp2[3];
                ull w0 = q0.x, w1 = q0.y, w2 = q1.x, w3 = q1.y;
                ull w4 = q2.x, w5 = q2.y, w6 = q3.x, w7 = q3.y;
                ull w8 = wbase[8];
                #pragma unroll
                for (int yy = 0; yy < PY; yy++)
                    #pragma unroll
                    for (int xp = 0; xp < NP; xp++) {
                        ull a = acc2[cl][yy][xp];
                        fma2(a, w0, inp[yy + 0][2 * xp + 0]);
                        fma2(a, w1, inp[yy + 0][2 * xp + 1]);
                        fma2(a, w2, inp[yy + 0][2 * xp + 2]);
                        fma2(a, w3, inp[yy + 1][2 * xp + 0]);
                        fma2(a, w4, inp[yy + 1][2 * xp + 1]);
                        fma2(a, w5, inp[yy + 1][2 * xp + 2]);
                        fma2(a, w6, inp[yy + 2][2 * xp + 0]);
                        fma2(a, w7, inp[yy + 2][2 * xp + 1]);
                        fma2(a, w8, inp[yy + 2][2 * xp + 2]);
                        acc2[cl][yy][xp] = a;
                    }
            }
        }
        __syncthreads();
    }

    // ---- epilogue: noise + bias + leaky relu, store
    float sn = __ldg(sn_ptr);
    float nz[PY][PX];
    #pragma unroll
    for (int yy = 0; yy < PY; yy++)
        #pragma unroll
        for (int xx = 0; xx < PX; xx++) {
            int gy = y0 + ly + yy, gx = x0 + lx + xx;
            nz[yy][xx] = sn * noise[((size_t)b * r + gy) * r + gx];
        }
    #pragma unroll
    for (int cl = 0; cl < 8; cl++) {
        int co = co0 + co_sub * 8 + cl;
        float bb = bias[co];
        float* op = xout + ((size_t)(b * NF + co)) * r * r;
        #pragma unroll
        for (int yy = 0; yy < PY; yy++)
            #pragma unroll
            for (int xp = 0; xp < NP; xp++) {
                float v0, v1;
                upk2(acc2[cl][yy][xp], v0, v1);
                int gy = y0 + ly + yy, gx = x0 + lx + xp * 2;
                float a0 = v0 + nz[yy][xp * 2 + 0] + bb;
                float a1 = v1 + nz[yy][xp * 2 + 1] + bb;
                a0 = a0 > 0.f ? a0 : 0.2f * a0;
                a1 = a1 > 0.f ? a1 : 0.2f * a1;
                *reinterpret_cast<float2*>(op + gy * r + gx) = make_float2(a0, a1);
            }
    }
}

// ---------------- ToRGB ------------------------------------------------------
__global__ void k_rgb(const float* __restrict__ xin, float* __restrict__ rgbout,
                      const float* __restrict__ rgb_w, int i, int r) {
    int b = blockIdx.y;
    __shared__ float wr[NF];
    if (threadIdx.x < NF) {
        const float cr = 0.08838834764831843f;  // 1/sqrt(128)
        wr[threadIdx.x] = rgb_w[i * NF + threadIdx.x] * cr * g_s[(i * BSZ + b) * NF + threadIdx.x];
    }
    __syncthreads();
    int p = blockIdx.x * blockDim.x + threadIdx.x;
    if (p >= r * r) return;
    const float* xp = xin + (size_t)b * NF * r * r + p;
    float acc = 0.f;
    #pragma unroll 4
    for (int ci = 0; ci < NF; ci++) acc += wr[ci] * xp[(size_t)ci * r * r];
    rgbout[(size_t)b * r * r + p] = acc;
}

// ---------------- final ------------------------------------------------------
__global__ void k_final(float* __restrict__ out) {
    int idx = blockIdx.x * blockDim.x + threadIdx.x;
    if (idx >= BSZ * IMG * IMG) return;
    int b = idx / (IMG * IMG);
    int rem = idx - b * (IMG * IMG);
    int y = rem >> 8, x = rem & 255;
    float sum = 0.f;
    int roff = 0;
    #pragma unroll
    for (int i = 0; i < 4; i++) {
        int r = 32 << i;
        const float* src = g_rgb + (size_t)BSZ * roff + (size_t)b * r * r;
        float sc = (float)r * (1.f / 256.f);
        float fy = (y + 0.5f) * sc - 0.5f;
        float fx = (x + 0.5f) * sc - 0.5f;
        int iy0 = (int)floorf(fy), ix0 = (int)floorf(fx);
        float ty = fy - iy0, tx = fx - ix0;
        int y0c = max(iy0, 0), y1c = min(iy0 + 1, r - 1);
        int x0c = max(ix0, 0), x1c = min(ix0 + 1, r - 1);
        float v00 = src[y0c * r + x0c], v01 = src[y0c * r + x1c];
        float v10 = src[y1c * r + x0c], v11 = src[y1c * r + x1c];
        float v0 = v00 + tx * (v01 - v00);
        float v1 = v10 + tx * (v11 - v10);
        sum += v0 + ty * (v1 - v0);
        roff += r * r;
    }
    out[idx] = sum * 0.5f + 0.5f;
}

// =============================================================================
static inline int conv_smem_bytes(int TX, int TY) {
    int in_ull = 8 * (TY + 2) * (TX + 3);
    int w_ull = 32 * 8 * 10;
    return (in_ull + w_ull) * 8;
}

extern "C" void kernel_launch(void* const* d_in, const int* in_sizes, int n_in,
                              void* d_out, int out_size) {
    const float* w      = (const float*)d_in[0];
    const float* noise_in[4] = { (const float*)d_in[1], (const float*)d_in[2],
                                 (const float*)d_in[3], (const float*)d_in[4] };
    const float* ic     = (const float*)d_in[5];
    const float* tsw    = (const float*)d_in[6];
    const float* tsb    = (const float*)d_in[7];
    const float* conv_w = (const float*)d_in[8];
    const float* sn     = (const float*)d_in[9];
    const float* sbias  = (const float*)d_in[10];
    const float* rgb_w  = (const float*)d_in[11];
    float* out = (float*)d_out;

    float *xa, *xb, *rgb;
    cudaGetSymbolAddress((void**)&xa, g_xa);
    cudaGetSymbolAddress((void**)&xb, g_xb);
    cudaGetSymbolAddress((void**)&rgb, g_rgb);

    const int smem_small = conv_smem_bytes(16, 8);
    const int smem_big   = conv_smem_bytes(32, 16);
    cudaFuncSetAttribute(k_conv<16, 8>,
                         cudaFuncAttributeMaxDynamicSharedMemorySize, smem_small);
    cudaFuncSetAttribute(k_conv<32, 16>,
                         cudaFuncAttributeMaxDynamicSharedMemorySize, smem_big);

    k_style<<<NB * BSZ, 128>>>(w, tsw, tsb);

    {
        int n = BSZ * NF * 32 * 32;
        k_init<<<(n + 255) / 256, 256>>>(ic, xa);
    }

    float* cur = xa;
    float* tmp = xb;
    int rgboff = 0;
    for (int i = 0; i < NB; i++) {
        int r = 32 << i;
        if (i > 0) {
            int n = BSZ * NF * r * r;
            k_up<<<(n + 255) / 256, 256>>>(cur, tmp, r / 2);
            float* t2 = cur; cur = tmp; tmp = t2;
        }
        for (int j = 0; j < 2; j++) {
            k_modw<<<BSZ * NF, 256>>>(conv_w, i, j);
            const float* nz = noise_in[i] + (size_t)j * BSZ * r * r;
            const float* snp = sn + (i * 2 + j);
            const float* bp = sbias + (i * 2 + j) * NF;
            if (r == 32) {
                dim3 grid(r / 16, r / 8, BSZ * 4);
                k_conv<16, 8><<<grid, 256, smem_small>>>(cur, tmp, nz, snp, bp, r);
            } else {
                dim3 grid(r / 32, r / 16, BSZ * 4);
                k_conv<32, 16><<<grid, 256, smem_big>>>(cur, tmp, nz, snp, bp, r);
            }
            float* t2 = cur; cur = tmp; tmp = t2;
        }
        dim3 rg((r * r + 255) / 256, BSZ);
        k_rgb<<<rg, 256>>>(cur, rgb + (size_t)BSZ * rgboff, rgb_w, i, r);
        rgboff += r * r;
    }

    {
        int n = BSZ * IMG * IMG;
        k_final<<<(n + 255) / 256, 256>>>(out);
    }
}

// round 7
// speedup vs baseline: 1.0136x; 1.0136x over previous
#include <cuda_runtime.h>
#include <math.h>

#define NB   4
#define BSZ  8
#define NF   128
#define WDIM 512
#define IMG  256

typedef unsigned long long ull;

// ---------------- packed f32x2 helpers (Blackwell) ---------------------------
__device__ __forceinline__ ull pk2(float lo, float hi) {
    ull r; asm("mov.b64 %0, {%1, %2};" : "=l"(r) : "f"(lo), "f"(hi)); return r;
}
__device__ __forceinline__ void upk2(ull v, float& lo, float& hi) {
    asm("mov.b64 {%0, %1}, %2;" : "=f"(lo), "=f"(hi) : "l"(v));
}
__device__ __forceinline__ void fma2(ull& d, ull a, ull b) {
    asm("fma.rn.f32x2 %0, %1, %2, %0;" : "+l"(d) : "l"(a), "l"(b));
}

// ---------------- scratch (static device globals; no allocation) -------------
__device__ float g_xa[BSZ * NF * IMG * IMG];
__device__ float g_xb[BSZ * NF * IMG * IMG];
__device__ float g_ws[BSZ * NF * NF * 9];
__device__ float g_s[NB * BSZ * NF];
__device__ float g_rgb[BSZ * (32*32 + 64*64 + 128*128 + 256*256)];

// ---------------- styles -----------------------------------------------------
__global__ void k_style(const float* __restrict__ w, const float* __restrict__ tsw,
                        const float* __restrict__ tsb) {
    int i = blockIdx.x / BSZ, b = blockIdx.x % BSZ;
    int c = threadIdx.x;
    __shared__ float sw[WDIM];
    for (int d = threadIdx.x; d < WDIM; d += blockDim.x)
        sw[d] = w[(i * BSZ + b) * WDIM + d];
    __syncthreads();
    const float* tw = tsw + (i * NF + c) * WDIM;
    float acc = 0.f;
    #pragma unroll 4
    for (int d = 0; d < WDIM; d++) acc += sw[d] * tw[d];
    const float cl = 0.044194173824159216f;   // 1/sqrt(512)
    g_s[(i * BSZ + b) * NF + c] = acc * cl + tsb[i * NF + c];
}

// ---------------- modulated + demodulated weights ----------------------------
__global__ void k_modw(const float* __restrict__ conv_w, int i, int j) {
    int b = blockIdx.x / NF, co = blockIdx.x % NF;
    const float* wsrc = conv_w + (((size_t)(i * 2 + j) * NF + co) * NF) * 9;
    const float* s = g_s + (i * BSZ + b) * NF;
    const float c = 0.029462782549439483f;    // 1/sqrt(128*9)
    __shared__ float buf[NF * 9];
    __shared__ float red[32];
    float ss = 0.f;
    for (int t = threadIdx.x; t < NF * 9; t += blockDim.x) {
        float v = wsrc[t] * c * s[t / 9];
        buf[t] = v;
        ss += v * v;
    }
    for (int o = 16; o; o >>= 1) ss += __shfl_xor_sync(0xffffffffu, ss, o);
    if ((threadIdx.x & 31) == 0) red[threadIdx.x >> 5] = ss;
    __syncthreads();
    if (threadIdx.x < 32) {
        float v = (threadIdx.x < (blockDim.x >> 5)) ? red[threadIdx.x] : 0.f;
        for (int o = 16; o; o >>= 1) v += __shfl_xor_sync(0xffffffffu, v, o);
        if (threadIdx.x == 0) red[0] = v;
    }
    __syncthreads();
    float dem = rsqrtf(red[0] + 1e-8f);
    float* dst = g_ws + ((size_t)(b * NF) + co) * (NF * 9);
    for (int t = threadIdx.x; t < NF * 9; t += blockDim.x) dst[t] = buf[t] * dem;
}

// ---------------- initial constant -------------------------------------------
__global__ void k_init(const float* __restrict__ ic, float* __restrict__ x) {
    int idx = blockIdx.x * blockDim.x + threadIdx.x;
    if (idx >= BSZ * NF * 32 * 32) return;
    int per = NF * 32 * 32;
    float v = ic[idx % per];
    x[idx] = v > 0.f ? v : 0.f;
}

// ---------------- bilinear 2x upsample ---------------------------------------
__global__ void k_up(const float* __restrict__ in, float* __restrict__ out, int rin) {
    int rout = rin * 2;
    int idx = blockIdx.x * blockDim.x + threadIdx.x;
    int total = BSZ * NF * rout * rout;
    if (idx >= total) return;
    int x = idx % rout;
    int t2 = idx / rout;
    int y = t2 % rout;
    int bc = t2 / rout;
    float fy = y * 0.5f - 0.25f, fx = x * 0.5f - 0.25f;
    int iy0 = (int)floorf(fy), ix0 = (int)floorf(fx);
    float ty = fy - iy0, tx = fx - ix0;
    int y0c = max(iy0, 0), y1c = min(iy0 + 1, rin - 1);
    int x0c = max(ix0, 0), x1c = min(ix0 + 1, rin - 1);
    const float* p = in + (size_t)bc * rin * rin;
    float v00 = p[y0c * rin + x0c], v01 = p[y0c * rin + x1c];
    float v10 = p[y1c * rin + x0c], v11 = p[y1c * rin + x1c];
    float v0 = v00 + tx * (v01 - v00);
    float v1 = v10 + tx * (v11 - v10);
    out[idx] = v0 + ty * (v1 - v0);
}

// ---------------- modulated conv3x3, f32x2, pre-paired smem ------------------
// __launch_bounds__(256, 1): ONE CTA per SM -> ptxas register budget 255,
// keeping the ~160-reg accumulator/input/weight tile fully in registers
// (R5's no-minBlocks build got 40 regs and spilled the whole tile to local).
template <int TX, int TY>
__global__ void __launch_bounds__(256, 1)
k_conv(const float* __restrict__ xin, float* __restrict__ xout,
       const float* __restrict__ noise, const float* __restrict__ sn_ptr,
       const float* __restrict__ bias, int r) {
    constexpr int PX = TX / 8;
    constexpr int PY = TY / 8;
    constexpr int NP = PX / 2;
    constexpr int PW = TX + 3;
    constexpr int IN_ULL = 8 * (TY + 2) * PW;

    extern __shared__ ull dyn[];
    ull* s_in = dyn;                       // [8][TY+2][PW]
    ull* s_w  = dyn + IN_ULL;              // [32][8][10]

    int bz = blockIdx.z;
    int b = bz >> 2, cg = bz & 3;
    int x0 = blockIdx.x * TX, y0 = blockIdx.y * TY;
    int t = threadIdx.x;
    int co_sub = t >> 6, pix = t & 63;
    int lx = (pix & 7) * PX, ly = (pix >> 3) * PY;
    int co0 = cg * 32;

    ull acc2[8][PY][NP];
    #pragma unroll
    for (int a = 0; a < 8; a++)
        #pragma unroll
        for (int yy = 0; yy < PY; yy++)
            #pragma unroll
            for (int xp = 0; xp < NP; xp++) acc2[a][yy][xp] = 0ull;

    const size_t ws_b = (size_t)b * NF * (NF * 9);

    for (int c0 = 0; c0 < NF; c0 += 8) {
        // ---- weights: 32co x 8ci x 9, pre-packed {w,w}, padded stride 10
        {
            int co_l = t >> 3, ci_l = t & 7;
            const float* src = g_ws + ws_b + ((size_t)(co0 + co_l) * NF + (c0 + ci_l)) * 9;
            ull* dst = s_w + (co_l * 8 + ci_l) * 10;
            #pragma unroll
            for (int k = 0; k < 9; k++) { float w = src[k]; dst[k] = pk2(w, w); }
        }
        // ---- pre-paired input tile: 8ci x (TY+2) x (TX+1) pairs, zero padded
        for (int e = t; e < 8 * (TY + 2) * (TX + 1); e += 256) {
            int ci_l = e / ((TY + 2) * (TX + 1));
            int rem = e - ci_l * ((TY + 2) * (TX + 1));
            int sy = rem / (TX + 1), sx = rem - sy * (TX + 1);
            int gy = y0 + sy - 1, gxa = x0 + sx - 1;
            float v0 = 0.f, v1 = 0.f;
            if (gy >= 0 && gy < r) {
                const float* row = xin + (((size_t)(b * NF + c0 + ci_l)) * r + gy) * r;
                if (gxa >= 0 && gxa < r) v0 = row[gxa];
                if (gxa + 1 < r)          v1 = row[gxa + 1];
            }
            s_in[(ci_l * (TY + 2) + sy) * PW + sx] = pk2(v0, v1);
        }
        __syncthreads();

        #pragma unroll
        for (int ci = 0; ci < 8; ci++) {
            ull inp[PY + 2][PX + 1];
            #pragma unroll
            for (int row = 0; row < PY + 2; row++)
                #pragma unroll
                for (int d = 0; d < PX + 1; d++)
                    inp[row][d] = s_in[(ci * (TY + 2) + ly + row) * PW + lx + d];
            #pragma unroll
            for (int cl = 0; cl < 8; cl++) {
                const ull* wbase = s_w + ((co_sub * 8 + cl) * 8 + ci) * 10;
                const ulong2* wp2 = reinterpret_cast<const ulong2*>(wbase);
                ulong2 q0 = wp2[0], q1 = wp2[1], q2 = wp2[2], q3 = wp2[3];
                ull w0 = q0.x, w1 = q0.y, w2 = q1.x, w3 = q1.y;
                ull w4 = q2.x, w5 = q2.y, w6 = q3.x, w7 = q3.y;
                ull w8 = wbase[8];
                #pragma unroll
                for (int yy = 0; yy < PY; yy++)
                    #pragma unroll
                    for (int xp = 0; xp < NP; xp++) {
                        ull a = acc2[cl][yy][xp];
                        fma2(a, w0, inp[yy + 0][2 * xp + 0]);
                        fma2(a, w1, inp[yy + 0][2 * xp + 1]);
                        fma2(a, w2, inp[yy + 0][2 * xp + 2]);
                        fma2(a, w3, inp[yy + 1][2 * xp + 0]);
                        fma2(a, w4, inp[yy + 1][2 * xp + 1]);
                        fma2(a, w5, inp[yy + 1][2 * xp + 2]);
                        fma2(a, w6, inp[yy + 2][2 * xp + 0]);
                        fma2(a, w7, inp[yy + 2][2 * xp + 1]);
                        fma2(a, w8, inp[yy + 2][2 * xp + 2]);
                        acc2[cl][yy][xp] = a;
                    }
            }
        }
        __syncthreads();
    }

    // ---- epilogue: noise + bias + leaky relu, store
    float sn = __ldg(sn_ptr);
    float nz[PY][PX];
    #pragma unroll
    for (int yy = 0; yy < PY; yy++)
        #pragma unroll
        for (int xx = 0; xx < PX; xx++) {
            int gy = y0 + ly + yy, gx = x0 + lx + xx;
            nz[yy][xx] = sn * noise[((size_t)b * r + gy) * r + gx];
        }
    #pragma unroll
    for (int cl = 0; cl < 8; cl++) {
        int co = co0 + co_sub * 8 + cl;
        float bb = bias[co];
        float* op = xout + ((size_t)(b * NF + co)) * r * r;
        #pragma unroll
        for (int yy = 0; yy < PY; yy++)
            #pragma unroll
            for (int xp = 0; xp < NP; xp++) {
                float v0, v1;
                upk2(acc2[cl][yy][xp], v0, v1);
                int gy = y0 + ly + yy, gx = x0 + lx + xp * 2;
                float a0 = v0 + nz[yy][xp * 2 + 0] + bb;
                float a1 = v1 + nz[yy][xp * 2 + 1] + bb;
                a0 = a0 > 0.f ? a0 : 0.2f * a0;
                a1 = a1 > 0.f ? a1 : 0.2f * a1;
                *reinterpret_cast<float2*>(op + gy * r + gx) = make_float2(a0, a1);
            }
    }
}

// ---------------- ToRGB ------------------------------------------------------
__global__ void k_rgb(const float* __restrict__ xin, float* __restrict__ rgbout,
                      const float* __restrict__ rgb_w, int i, int r) {
    int b = blockIdx.y;
    __shared__ float wr[NF];
    if (threadIdx.x < NF) {
        const float cr = 0.08838834764831843f;  // 1/sqrt(128)
        wr[threadIdx.x] = rgb_w[i * NF + threadIdx.x] * cr * g_s[(i * BSZ + b) * NF + threadIdx.x];
    }
    __syncthreads();
    int p = blockIdx.x * blockDim.x + threadIdx.x;
    if (p >= r * r) return;
    const float* xp = xin + (size_t)b * NF * r * r + p;
    float acc = 0.f;
    #pragma unroll 4
    for (int ci = 0; ci < NF; ci++) acc += wr[ci] * xp[(size_t)ci * r * r];
    rgbout[(size_t)b * r * r + p] = acc;
}

// ---------------- final ------------------------------------------------------
__global__ void k_final(float* __restrict__ out) {
    int idx = blockIdx.x * blockDim.x + threadIdx.x;
    if (idx >= BSZ * IMG * IMG) return;
    int b = idx / (IMG * IMG);
    int rem = idx - b * (IMG * IMG);
    int y = rem >> 8, x = rem & 255;
    float sum = 0.f;
    int roff = 0;
    #pragma unroll
    for (int i = 0; i < 4; i++) {
        int r = 32 << i;
        const float* src = g_rgb + (size_t)BSZ * roff + (size_t)b * r * r;
        float sc = (float)r * (1.f / 256.f);
        float fy = (y + 0.5f) * sc - 0.5f;
        float fx = (x + 0.5f) * sc - 0.5f;
        int iy0 = (int)floorf(fy), ix0 = (int)floorf(fx);
        float ty = fy - iy0, tx = fx - ix0;
        int y0c = max(iy0, 0), y1c = min(iy0 + 1, r - 1);
        int x0c = max(ix0, 0), x1c = min(ix0 + 1, r - 1);
        float v00 = src[y0c * r + x0c], v01 = src[y0c * r + x1c];
        float v10 = src[y1c * r + x0c], v11 = src[y1c * r + x1c];
        float v0 = v00 + tx * (v01 - v00);
        float v1 = v10 + tx * (v11 - v10);
        sum += v0 + ty * (v1 - v0);
        roff += r * r;
    }
    out[idx] = sum * 0.5f + 0.5f;
}

// =============================================================================
static inline int conv_smem_bytes(int TX, int TY) {
    int in_ull = 8 * (TY + 2) * (TX + 3);
    int w_ull = 32 * 8 * 10;
    return (in_ull + w_ull) * 8;
}

extern "C" void kernel_launch(void* const* d_in, const int* in_sizes, int n_in,
                              void* d_out, int out_size) {
    const float* w      = (const float*)d_in[0];
    const float* noise_in[4] = { (const float*)d_in[1], (const float*)d_in[2],
                                 (const float*)d_in[3], (const float*)d_in[4] };
    const float* ic     = (const float*)d_in[5];
    const float* tsw    = (const float*)d_in[6];
    const float* tsb    = (const float*)d_in[7];
    const float* conv_w = (const float*)d_in[8];
    const float* sn     = (const float*)d_in[9];
    const float* sbias  = (const float*)d_in[10];
    const float* rgb_w  = (const float*)d_in[11];
    float* out = (float*)d_out;

    float *xa, *xb, *rgb;
    cudaGetSymbolAddress((void**)&xa, g_xa);
    cudaGetSymbolAddress((void**)&xb, g_xb);
    cudaGetSymbolAddress((void**)&rgb, g_rgb);

    const int smem_small = conv_smem_bytes(16, 8);
    const int smem_big   = conv_smem_bytes(32, 16);
    cudaFuncSetAttribute(k_conv<16, 8>,
                         cudaFuncAttributeMaxDynamicSharedMemorySize, smem_small);
    cudaFuncSetAttribute(k_conv<32, 16>,
                         cudaFuncAttributeMaxDynamicSharedMemorySize, smem_big);

    k_style<<<NB * BSZ, 128>>>(w, tsw, tsb);

    {
        int n = BSZ * NF * 32 * 32;
        k_init<<<(n + 255) / 256, 256>>>(ic, xa);
    }

    float* cur = xa;
    float* tmp = xb;
    int rgboff = 0;
    for (int i = 0; i < NB; i++) {
        int r = 32 << i;
        if (i > 0) {
            int n = BSZ * NF * r * r;
            k_up<<<(n + 255) / 256, 256>>>(cur, tmp, r / 2);
            float* t2 = cur; cur = tmp; tmp = t2;
        }
        for (int j = 0; j < 2; j++) {
            k_modw<<<BSZ * NF, 256>>>(conv_w, i, j);
            const float* nz = noise_in[i] + (size_t)j * BSZ * r * r;
            const float* snp = sn + (i * 2 + j);
            const float* bp = sbias + (i * 2 + j) * NF;
            if (r == 32) {
                dim3 grid(r / 16, r / 8, BSZ * 4);
                k_conv<16, 8><<<grid, 256, smem_small>>>(cur, tmp, nz, snp, bp, r);
            } else {
                dim3 grid(r / 32, r / 16, BSZ * 4);
                k_conv<32, 16><<<grid, 256, smem_big>>>(cur, tmp, nz, snp, bp, r);
            }
            float* t2 = cur; cur = tmp; tmp = t2;
        }
        dim3 rg((r * r + 255) / 256, BSZ);
        k_rgb<<<rg, 256>>>(cur, rgb + (size_t)BSZ * rgboff, rgb_w, i, r);
        rgboff += r * r;
    }

    {
        int n = BSZ * IMG * IMG;
        k_final<<<(n + 255) / 256, 256>>>(out);
    }
}

// round 8
// speedup vs baseline: 2.9148x; 2.8757x over previous
#include <cuda_runtime.h>
#include <cuda_bf16.h>
#include <math.h>

#define NB   4
#define BSZ  8
#define NF   128
#define WDIM 512
#define IMG  256

// ---------------- scratch (static device globals; no allocation) -------------
__device__ float g_xa[BSZ * NF * IMG * IMG];
__device__ float g_xb[BSZ * NF * IMG * IMG];
__device__ float g_s[NB * BSZ * NF];
__device__ float g_rgb[BSZ * (32*32 + 64*64 + 128*128 + 256*256)];
// pre-split modulated weights, MMA-pair layout: [b][chunk(ci/16)][co][tap k][ci2 pair]
// per (b,chunk) block = 128co * 72 u32 (k*8+p), u32 = {bf16(ci even), bf16(ci odd)}
__device__ unsigned int g_wsh[BSZ * 8 * NF * 72];
__device__ unsigned int g_wsl[BSZ * 8 * NF * 72];

// ---------------- bf16 split helpers -----------------------------------------
__device__ __forceinline__ void split2(float v0, float v1,
                                       unsigned int& hi, unsigned int& lo) {
    __nv_bfloat16 h0 = __float2bfloat16(v0);
    __nv_bfloat16 h1 = __float2bfloat16(v1);
    float r0 = v0 - __bfloat162float(h0);
    float r1 = v1 - __bfloat162float(h1);
    __nv_bfloat16 l0 = __float2bfloat16(r0);
    __nv_bfloat16 l1 = __float2bfloat16(r1);
    hi = (unsigned int)__bfloat16_as_ushort(h0) |
         ((unsigned int)__bfloat16_as_ushort(h1) << 16);
    lo = (unsigned int)__bfloat16_as_ushort(l0) |
         ((unsigned int)__bfloat16_as_ushort(l1) << 16);
}

__device__ __forceinline__ void mma16816(float* d, const unsigned int* a,
                                         const unsigned int* b) {
    asm volatile(
        "mma.sync.aligned.m16n8k16.row.col.f32.bf16.bf16.f32 "
        "{%0,%1,%2,%3}, {%4,%5,%6,%7}, {%8,%9}, {%0,%1,%2,%3};\n"
        : "+f"(d[0]), "+f"(d[1]), "+f"(d[2]), "+f"(d[3])
        : "r"(a[0]), "r"(a[1]), "r"(a[2]), "r"(a[3]), "r"(b[0]), "r"(b[1]));
}

// ---------------- styles -----------------------------------------------------
__global__ void k_style(const float* __restrict__ w, const float* __restrict__ tsw,
                        const float* __restrict__ tsb) {
    int i = blockIdx.x / BSZ, b = blockIdx.x % BSZ;
    int c = threadIdx.x;
    __shared__ float sw[WDIM];
    for (int d = threadIdx.x; d < WDIM; d += blockDim.x)
        sw[d] = w[(i * BSZ + b) * WDIM + d];
    __syncthreads();
    const float* tw = tsw + (i * NF + c) * WDIM;
    float acc = 0.f;
    #pragma unroll 4
    for (int d = 0; d < WDIM; d++) acc += sw[d] * tw[d];
    const float cl = 0.044194173824159216f;   // 1/sqrt(512)
    g_s[(i * BSZ + b) * NF + c] = acc * cl + tsb[i * NF + c];
}

// ---- modulated + demodulated weights -> pre-split bf16 hi/lo, pair layout ---
__global__ void k_modw(const float* __restrict__ conv_w, int i, int j) {
    int b = blockIdx.x / NF, co = blockIdx.x % NF;
    const float* wsrc = conv_w + (((size_t)(i * 2 + j) * NF + co) * NF) * 9;
    const float* s = g_s + (i * BSZ + b) * NF;
    const float c = 0.029462782549439483f;    // 1/sqrt(128*9)
    __shared__ float buf[NF * 9];
    __shared__ float red[32];
    float ss = 0.f;
    for (int t = threadIdx.x; t < NF * 9; t += blockDim.x) {
        float v = wsrc[t] * c * s[t / 9];
        buf[t] = v;
        ss += v * v;
    }
    for (int o = 16; o; o >>= 1) ss += __shfl_xor_sync(0xffffffffu, ss, o);
    if ((threadIdx.x & 31) == 0) red[threadIdx.x >> 5] = ss;
    __syncthreads();
    if (threadIdx.x < 32) {
        float v = (threadIdx.x < (blockDim.x >> 5)) ? red[threadIdx.x] : 0.f;
        for (int o = 16; o; o >>= 1) v += __shfl_xor_sync(0xffffffffu, v, o);
        if (threadIdx.x == 0) red[0] = v;
    }
    __syncthreads();
    float dem = rsqrtf(red[0] + 1e-8f);
    // write pairs: entry e -> ci2g = e/9 (0..63), tap k = e%9
    for (int e = threadIdx.x; e < 576; e += blockDim.x) {
        int ci2g = e / 9, k = e - ci2g * 9;
        int ci = ci2g * 2;
        float v0 = buf[ci * 9 + k] * dem;
        float v1 = buf[ci * 9 + 9 + k] * dem;
        unsigned int hi, lo;
        split2(v0, v1, hi, lo);
        int chunk = ci2g >> 3, p = ci2g & 7;
        size_t idx = (((size_t)(b * 8 + chunk) * NF + co) * 9 + k) * 8 + p;
        g_wsh[idx] = hi;
        g_wsl[idx] = lo;
    }
}

// ---------------- initial constant -------------------------------------------
__global__ void k_init(const float* __restrict__ ic, float* __restrict__ x) {
    int idx = blockIdx.x * blockDim.x + threadIdx.x;
    if (idx >= BSZ * NF * 32 * 32) return;
    int per = NF * 32 * 32;
    float v = ic[idx % per];
    x[idx] = v > 0.f ? v : 0.f;
}

// ---------------- bilinear 2x upsample ---------------------------------------
__global__ void k_up(const float* __restrict__ in, float* __restrict__ out, int rin) {
    int rout = rin * 2;
    int idx = blockIdx.x * blockDim.x + threadIdx.x;
    int total = BSZ * NF * rout * rout;
    if (idx >= total) return;
    int x = idx % rout;
    int t2 = idx / rout;
    int y = t2 % rout;
    int bc = t2 / rout;
    float fy = y * 0.5f - 0.25f, fx = x * 0.5f - 0.25f;
    int iy0 = (int)floorf(fy), ix0 = (int)floorf(fx);
    float ty = fy - iy0, tx = fx - ix0;
    int y0c = max(iy0, 0), y1c = min(iy0 + 1, rin - 1);
    int x0c = max(ix0, 0), x1c = min(ix0 + 1, rin - 1);
    const float* p = in + (size_t)bc * rin * rin;
    float v00 = p[y0c * rin + x0c], v01 = p[y0c * rin + x1c];
    float v10 = p[y1c * rin + x0c], v11 = p[y1c * rin + x1c];
    float v0 = v00 + tx * (v01 - v00);
    float v1 = v10 + tx * (v11 - v10);
    out[idx] = v0 + ty * (v1 - v0);
}

// ---------------- tensor-core modulated conv3x3 ------------------------------
// CTA: 128 co x 128 px (8 rows x 16 cols spatial). 256 threads = 8 warps, each
// warp: 16 co x 128 px via mma.sync m16n8k16 bf16 (hi/lo split, 3 MMAs).
// Dyn smem (u32):
//   s_wh [128co][76]   (72 used: tap k*8 + ci-pair; stride 76 -> conflict-free)
//   s_wl same
//   s_xh [10 py][18 px * 12-stride][8 ci-pairs]  (halo tile, pair-packed)
//   s_xl same
#define W_STRIDE   76
#define S_WH_OFF   0
#define S_WL_OFF   (NF * W_STRIDE)               // 9728
#define X_PXS      12
#define X_PYS      (18 * X_PXS)                  // 216
#define S_XH_OFF   (2 * NF * W_STRIDE)           // 19456
#define S_XL_OFF   (S_XH_OFF + 10 * X_PYS)       // +2160
#define CONV_SMEM_U32 (S_XL_OFF + 10 * X_PYS)
#define CONV_SMEM_B   (CONV_SMEM_U32 * 4)        // 95104 bytes

__global__ void __launch_bounds__(256, 1)
k_conv_mma(const float* __restrict__ xin, float* __restrict__ xout,
           const float* __restrict__ noise, const float* __restrict__ sn_ptr,
           const float* __restrict__ bias, int r) {
    extern __shared__ unsigned int dyn[];
    unsigned int* s_wh = dyn + S_WH_OFF;
    unsigned int* s_wl = dyn + S_WL_OFF;
    unsigned int* s_xh = dyn + S_XH_OFF;
    unsigned int* s_xl = dyn + S_XL_OFF;

    int b = blockIdx.z;
    int x0 = blockIdx.x * 16, y0 = blockIdx.y * 8;
    int t = threadIdx.x;
    int warp = t >> 5, lane = t & 31;
    int co_w = warp * 16;
    int lq = lane >> 2;          // groupID (0..7)
    int lr = lane & 3;           // thread-in-group (0..3)

    float acc[16][4];
    #pragma unroll
    for (int g = 0; g < 16; g++)
        #pragma unroll
        for (int q = 0; q < 4; q++) acc[g][q] = 0.f;

    #pragma unroll 1
    for (int chunk = 0; chunk < 8; chunk++) {
        // ---- weights: coalesced uint4 copy, restride 72 -> 76
        {
            size_t base4 = (size_t)(b * 8 + chunk) * (NF * 72 / 4);
            const uint4* gh = reinterpret_cast<const uint4*>(g_wsh) + base4;
            const uint4* gl = reinterpret_cast<const uint4*>(g_wsl) + base4;
            for (int e4 = t; e4 < NF * 18; e4 += 256) {
                int co = e4 / 18, rem = e4 - co * 18;
                *reinterpret_cast<uint4*>(&s_wh[co * W_STRIDE + rem * 4]) = gh[e4];
                *reinterpret_cast<uint4*>(&s_wl[co * W_STRIDE + rem * 4]) = gl[e4];
            }
        }
        // ---- input halo tile 10x18, 16 ci (8 pairs), split to bf16 hi/lo
        for (int e = t; e < 10 * 18 * 8; e += 256) {
            int p = e & 7;
            int t2 = e >> 3;
            int px = t2 % 18, py = t2 / 18;
            int gy = y0 + py - 1, gx = x0 + px - 1;
            int ci = chunk * 16 + 2 * p;
            float v0 = 0.f, v1 = 0.f;
            if (gy >= 0 && gy < r && gx >= 0 && gx < r) {
                const float* pp = xin + (((size_t)(b * NF + ci)) * r + gy) * r + gx;
                v0 = pp[0];
                v1 = pp[(size_t)r * r];
            }
            unsigned int hi, lo;
            split2(v0, v1, hi, lo);
            int off = py * X_PYS + px * X_PXS + p;
            s_xh[off] = hi;
            s_xl[off] = lo;
        }
        __syncthreads();

        #pragma unroll 1
        for (int off = 0; off < 9; off++) {
            int ky = off / 3, kx = off - ky * 3;
            int wbase = (co_w + lq) * W_STRIDE + off * 8 + lr;
            unsigned int ah[4], al[4];
            ah[0] = s_wh[wbase];
            ah[1] = s_wh[wbase + 8 * W_STRIDE];
            ah[2] = s_wh[wbase + 4];
            ah[3] = s_wh[wbase + 8 * W_STRIDE + 4];
            al[0] = s_wl[wbase];
            al[1] = s_wl[wbase + 8 * W_STRIDE];
            al[2] = s_wl[wbase + 4];
            al[3] = s_wl[wbase + 8 * W_STRIDE + 4];
            int xbase = ky * X_PYS + (lq + kx) * X_PXS + lr;
            #pragma unroll
            for (int g = 0; g < 16; g++) {
                int xb = xbase + (g >> 1) * X_PYS + (g & 1) * (8 * X_PXS);
                unsigned int bh[2], bl[2];
                bh[0] = s_xh[xb];
                bh[1] = s_xh[xb + 4];
                bl[0] = s_xl[xb];
                bl[1] = s_xl[xb + 4];
                mma16816(acc[g], ah, bh);
                mma16816(acc[g], ah, bl);
                mma16816(acc[g], al, bh);
            }
        }
        __syncthreads();
    }

    // ---- epilogue: noise + bias + leaky relu
    float sn = __ldg(sn_ptr);
    int co0 = co_w + lq, co1 = co0 + 8;
    float bb0 = bias[co0], bb1 = bias[co1];
    float* op0 = xout + ((size_t)(b * NF + co0)) * r * r;
    float* op1 = xout + ((size_t)(b * NF + co1)) * r * r;
    #pragma unroll
    for (int g = 0; g < 16; g++) {
        int gy = y0 + (g >> 1);
        int gx = x0 + (g & 1) * 8 + 2 * lr;
        const float* np = noise + ((size_t)b * r + gy) * r + gx;
        float n0 = sn * np[0], n1 = sn * np[1];
        float u0 = acc[g][0] + n0 + bb0;
        float u1 = acc[g][1] + n1 + bb0;
        float u2 = acc[g][2] + n0 + bb1;
        float u3 = acc[g][3] + n1 + bb1;
        u0 = u0 > 0.f ? u0 : 0.2f * u0;
        u1 = u1 > 0.f ? u1 : 0.2f * u1;
        u2 = u2 > 0.f ? u2 : 0.2f * u2;
        u3 = u3 > 0.f ? u3 : 0.2f * u3;
        *reinterpret_cast<float2*>(op0 + (size_t)gy * r + gx) = make_float2(u0, u1);
        *reinterpret_cast<float2*>(op1 + (size_t)gy * r + gx) = make_float2(u2, u3);
    }
}

// ---------------- ToRGB ------------------------------------------------------
__global__ void k_rgb(const float* __restrict__ xin, float* __restrict__ rgbout,
                      const float* __restrict__ rgb_w, int i, int r) {
    int b = blockIdx.y;
    __shared__ float wr[NF];
    if (threadIdx.x < NF) {
        const float cr = 0.08838834764831843f;  // 1/sqrt(128)
        wr[threadIdx.x] = rgb_w[i * NF + threadIdx.x] * cr * g_s[(i * BSZ + b) * NF + threadIdx.x];
    }
    __syncthreads();
    int p = blockIdx.x * blockDim.x + threadIdx.x;
    if (p >= r * r) return;
    const float* xp = xin + (size_t)b * NF * r * r + p;
    float acc = 0.f;
    #pragma unroll 4
    for (int ci = 0; ci < NF; ci++) acc += wr[ci] * xp[(size_t)ci * r * r];
    rgbout[(size_t)b * r * r + p] = acc;
}

// ---------------- final ------------------------------------------------------
__global__ void k_final(float* __restrict__ out) {
    int idx = blockIdx.x * blockDim.x + threadIdx.x;
    if (idx >= BSZ * IMG * IMG) return;
    int b = idx / (IMG * IMG);
    int rem = idx - b * (IMG * IMG);
    int y = rem >> 8, x = rem & 255;
    float sum = 0.f;
    int roff = 0;
    #pragma unroll
    for (int i = 0; i < 4; i++) {
        int r = 32 << i;
        const float* src = g_rgb + (size_t)BSZ * roff + (size_t)b * r * r;
        float sc = (float)r * (1.f / 256.f);
        float fy = (y + 0.5f) * sc - 0.5f;
        float fx = (x + 0.5f) * sc - 0.5f;
        int iy0 = (int)floorf(fy), ix0 = (int)floorf(fx);
        float ty = fy - iy0, tx = fx - ix0;
        int y0c = max(iy0, 0), y1c = min(iy0 + 1, r - 1);
        int x0c = max(ix0, 0), x1c = min(ix0 + 1, r - 1);
        float v00 = src[y0c * r + x0c], v01 = src[y0c * r + x1c];
        float v10 = src[y1c * r + x0c], v11 = src[y1c * r + x1c];
        float v0 = v00 + tx * (v01 - v00);
        float v1 = v10 + tx * (v11 - v10);
        sum += v0 + ty * (v1 - v0);
        roff += r * r;
    }
    out[idx] = sum * 0.5f + 0.5f;
}

// =============================================================================
extern "C" void kernel_launch(void* const* d_in, const int* in_sizes, int n_in,
                              void* d_out, int out_size) {
    const float* w      = (const float*)d_in[0];
    const float* noise_in[4] = { (const float*)d_in[1], (const float*)d_in[2],
                                 (const float*)d_in[3], (const float*)d_in[4] };
    const float* ic     = (const float*)d_in[5];
    const float* tsw    = (const float*)d_in[6];
    const float* tsb    = (const float*)d_in[7];
    const float* conv_w = (const float*)d_in[8];
    const float* sn     = (const float*)d_in[9];
    const float* sbias  = (const float*)d_in[10];
    const float* rgb_w  = (const float*)d_in[11];
    float* out = (float*)d_out;

    float *xa, *xb, *rgb;
    cudaGetSymbolAddress((void**)&xa, g_xa);
    cudaGetSymbolAddress((void**)&xb, g_xb);
    cudaGetSymbolAddress((void**)&rgb, g_rgb);

    cudaFuncSetAttribute(k_conv_mma,
                         cudaFuncAttributeMaxDynamicSharedMemorySize, CONV_SMEM_B);

    k_style<<<NB * BSZ, 128>>>(w, tsw, tsb);

    {
        int n = BSZ * NF * 32 * 32;
        k_init<<<(n + 255) / 256, 256>>>(ic, xa);
    }

    float* cur = xa;
    float* tmp = xb;
    int rgboff = 0;
    for (int i = 0; i < NB; i++) {
        int r = 32 << i;
        if (i > 0) {
            int n = BSZ * NF * r * r;
            k_up<<<(n + 255) / 256, 256>>>(cur, tmp, r / 2);
            float* t2 = cur; cur = tmp; tmp = t2;
        }
        for (int j = 0; j < 2; j++) {
            k_modw<<<BSZ * NF, 256>>>(conv_w, i, j);
            const float* nz = noise_in[i] + (size_t)j * BSZ * r * r;
            const float* snp = sn + (i * 2 + j);
            const float* bp = sbias + (i * 2 + j) * NF;
            dim3 grid(r / 16, r / 8, BSZ);
            k_conv_mma<<<grid, 256, CONV_SMEM_B>>>(cur, tmp, nz, snp, bp, r);
            float* t2 = cur; cur = tmp; tmp = t2;
        }
        dim3 rg((r * r + 255) / 256, BSZ);
        k_rgb<<<rg, 256>>>(cur, rgb + (size_t)BSZ * rgboff, rgb_w, i, r);
        rgboff += r * r;
    }

    {
        int n = BSZ * IMG * IMG;
        k_final<<<(n + 255) / 256, 256>>>(out);
    }
}

// round 9
// speedup vs baseline: 3.7518x; 1.2872x over previous
#include <cuda_runtime.h>
#include <cuda_bf16.h>
#include <math.h>

#define NB   4
#define BSZ  8
#define NF   128
#define WDIM 512
#define IMG  256

// ---------------- scratch (static device globals; no allocation) -------------
__device__ float g_xa[BSZ * NF * IMG * IMG];
__device__ float g_xb[BSZ * NF * IMG * IMG];
__device__ float g_s[NB * BSZ * NF];
__device__ float g_rgb[BSZ * (32*32 + 64*64 + 128*128 + 256*256)];
// pre-split modulated weights, MMA-pair layout: [b][chunk(ci/16)][co][tap k][ci2 pair]
__device__ unsigned int g_wsh[BSZ * 8 * NF * 72];
__device__ unsigned int g_wsl[BSZ * 8 * NF * 72];

// ---------------- helpers ----------------------------------------------------
__device__ __forceinline__ void split2(float v0, float v1,
                                       unsigned int& hi, unsigned int& lo) {
    __nv_bfloat16 h0 = __float2bfloat16(v0);
    __nv_bfloat16 h1 = __float2bfloat16(v1);
    float r0 = v0 - __bfloat162float(h0);
    float r1 = v1 - __bfloat162float(h1);
    __nv_bfloat16 l0 = __float2bfloat16(r0);
    __nv_bfloat16 l1 = __float2bfloat16(r1);
    hi = (unsigned int)__bfloat16_as_ushort(h0) |
         ((unsigned int)__bfloat16_as_ushort(h1) << 16);
    lo = (unsigned int)__bfloat16_as_ushort(l0) |
         ((unsigned int)__bfloat16_as_ushort(l1) << 16);
}

__device__ __forceinline__ void mma16816(float* d, const unsigned int* a,
                                         const unsigned int* b) {
    asm volatile(
        "mma.sync.aligned.m16n8k16.row.col.f32.bf16.bf16.f32 "
        "{%0,%1,%2,%3}, {%4,%5,%6,%7}, {%8,%9}, {%0,%1,%2,%3};\n"
        : "+f"(d[0]), "+f"(d[1]), "+f"(d[2]), "+f"(d[3])
        : "r"(a[0]), "r"(a[1]), "r"(a[2]), "r"(a[3]), "r"(b[0]), "r"(b[1]));
}

__device__ __forceinline__ void cp16(unsigned int* smem_dst, const void* gsrc) {
    unsigned int sa = (unsigned int)__cvta_generic_to_shared(smem_dst);
    asm volatile("cp.async.cg.shared.global [%0], [%1], 16;\n"
                 :: "r"(sa), "l"(gsrc));
}
__device__ __forceinline__ void cp_commit() {
    asm volatile("cp.async.commit_group;\n");
}
__device__ __forceinline__ void cp_wait0() {
    asm volatile("cp.async.wait_group 0;\n");
}

// ---------------- styles -----------------------------------------------------
__global__ void k_style(const float* __restrict__ w, const float* __restrict__ tsw,
                        const float* __restrict__ tsb) {
    int i = blockIdx.x / BSZ, b = blockIdx.x % BSZ;
    int c = threadIdx.x;
    __shared__ float sw[WDIM];
    for (int d = threadIdx.x; d < WDIM; d += blockDim.x)
        sw[d] = w[(i * BSZ + b) * WDIM + d];
    __syncthreads();
    const float* tw = tsw + (i * NF + c) * WDIM;
    float acc = 0.f;
    #pragma unroll 4
    for (int d = 0; d < WDIM; d++) acc += sw[d] * tw[d];
    const float cl = 0.044194173824159216f;   // 1/sqrt(512)
    g_s[(i * BSZ + b) * NF + c] = acc * cl + tsb[i * NF + c];
}

// ---- modulated + demodulated weights -> pre-split bf16 hi/lo, pair layout ---
__global__ void k_modw(const float* __restrict__ conv_w, int i, int j) {
    int b = blockIdx.x / NF, co = blockIdx.x % NF;
    const float* wsrc = conv_w + (((size_t)(i * 2 + j) * NF + co) * NF) * 9;
    const float* s = g_s + (i * BSZ + b) * NF;
    const float c = 0.029462782549439483f;    // 1/sqrt(128*9)
    __shared__ float buf[NF * 9];
    __shared__ float red[32];
    float ss = 0.f;
    for (int t = threadIdx.x; t < NF * 9; t += blockDim.x) {
        float v = wsrc[t] * c * s[t / 9];
        buf[t] = v;
        ss += v * v;
    }
    for (int o = 16; o; o >>= 1) ss += __shfl_xor_sync(0xffffffffu, ss, o);
    if ((threadIdx.x & 31) == 0) red[threadIdx.x >> 5] = ss;
    __syncthreads();
    if (threadIdx.x < 32) {
        float v = (threadIdx.x < (blockDim.x >> 5)) ? red[threadIdx.x] : 0.f;
        for (int o = 16; o; o >>= 1) v += __shfl_xor_sync(0xffffffffu, v, o);
        if (threadIdx.x == 0) red[0] = v;
    }
    __syncthreads();
    float dem = rsqrtf(red[0] + 1e-8f);
    for (int e = threadIdx.x; e < 576; e += blockDim.x) {
        int ci2g = e / 9, k = e - ci2g * 9;
        int ci = ci2g * 2;
        float v0 = buf[ci * 9 + k] * dem;
        float v1 = buf[ci * 9 + 9 + k] * dem;
        unsigned int hi, lo;
        split2(v0, v1, hi, lo);
        int chunk = ci2g >> 3, p = ci2g & 7;
        size_t idx = (((size_t)(b * 8 + chunk) * NF + co) * 9 + k) * 8 + p;
        g_wsh[idx] = hi;
        g_wsl[idx] = lo;
    }
}

// ---------------- initial constant -------------------------------------------
__global__ void k_init(const float* __restrict__ ic, float* __restrict__ x) {
    int idx = blockIdx.x * blockDim.x + threadIdx.x;
    if (idx >= BSZ * NF * 32 * 32) return;
    int per = NF * 32 * 32;
    float v = ic[idx % per];
    x[idx] = v > 0.f ? v : 0.f;
}

// ---------------- bilinear 2x upsample ---------------------------------------
__global__ void k_up(const float* __restrict__ in, float* __restrict__ out, int rin) {
    int rout = rin * 2;
    int idx = blockIdx.x * blockDim.x + threadIdx.x;
    int total = BSZ * NF * rout * rout;
    if (idx >= total) return;
    int x = idx % rout;
    int t2 = idx / rout;
    int y = t2 % rout;
    int bc = t2 / rout;
    float fy = y * 0.5f - 0.25f, fx = x * 0.5f - 0.25f;
    int iy0 = (int)floorf(fy), ix0 = (int)floorf(fx);
    float ty = fy - iy0, tx = fx - ix0;
    int y0c = max(iy0, 0), y1c = min(iy0 + 1, rin - 1);
    int x0c = max(ix0, 0), x1c = min(ix0 + 1, rin - 1);
    const float* p = in + (size_t)bc * rin * rin;
    float v00 = p[y0c * rin + x0c], v01 = p[y0c * rin + x1c];
    float v10 = p[y1c * rin + x0c], v11 = p[y1c * rin + x1c];
    float v0 = v00 + tx * (v01 - v00);
    float v1 = v10 + tx * (v11 - v10);
    out[idx] = v0 + ty * (v1 - v0);
}

// ---------------- tensor-core modulated conv3x3, pipelined -------------------
// CTA: 128 co x (TPX x 8) px. 256 threads = 8 warps; warp = 16 co x all px.
// Double-buffered weights (cp.async) + register-prefetched x tile.
#define W_STRIDE 76
#define X_PXS    12
#define W_BUF_U32 (2 * NF * W_STRIDE)            // hi+lo for one chunk: 19456
#define W_TOTAL_U32 (2 * W_BUF_U32)              // two buffers: 38912

template <int TPX>
__global__ void __launch_bounds__(256, 1)
k_conv_mma(const float* __restrict__ xin, float* __restrict__ xout,
           const float* __restrict__ noise, const float* __restrict__ sn_ptr,
           const float* __restrict__ bias, int r) {
    constexpr int HW = TPX + 2;                  // halo width
    constexpr int X_PYS = HW * X_PXS;
    constexpr int NCB = TPX / 8;                 // 8-px column blocks (1 or 2)
    constexpr int E = 10 * HW * 8;               // x-tile entries (pairs)
    constexpr int MAXE = (E + 255) / 256;
    constexpr int XH_OFF = W_TOTAL_U32;
    constexpr int XL_OFF = XH_OFF + 10 * X_PYS;

    extern __shared__ unsigned int dyn[];

    int b = blockIdx.z;
    int x0 = blockIdx.x * TPX, y0 = blockIdx.y * 8;
    int t = threadIdx.x;
    int warp = t >> 5, lane = t & 31;
    int co_w = warp * 16;
    int lq = lane >> 2;
    int lr = lane & 3;

    const size_t rr = (size_t)r * r;

    float acc[8][NCB][4];
    #pragma unroll
    for (int row = 0; row < 8; row++)
        #pragma unroll
        for (int cb = 0; cb < NCB; cb++)
            #pragma unroll
            for (int q = 0; q < 4; q++) acc[row][cb][q] = 0.f;

    // ---- weight async copy helper (restride 72 -> 76), one chunk -> buf
    auto load_w = [&](int chunk, int buf) {
        size_t base4 = (size_t)(b * 8 + chunk) * (NF * 18);
        const uint4* gh = reinterpret_cast<const uint4*>(g_wsh) + base4;
        const uint4* gl = reinterpret_cast<const uint4*>(g_wsl) + base4;
        unsigned int* wh = dyn + buf * W_BUF_U32;
        unsigned int* wl = wh + NF * W_STRIDE;
        for (int e4 = t; e4 < NF * 18; e4 += 256) {
            int co = e4 / 18, rem = e4 - co * 18;
            cp16(&wh[co * W_STRIDE + rem * 4], gh + e4);
            cp16(&wl[co * W_STRIDE + rem * 4], gl + e4);
        }
    };

    float pv0[MAXE], pv1[MAXE];
    // ---- x prefetch (gmem -> regs) for a chunk
    auto fetch_x = [&](int chunk) {
        #pragma unroll
        for (int i = 0; i < MAXE; i++) {
            int e = t + i * 256;
            float v0 = 0.f, v1 = 0.f;
            if (e < E) {
                int p = e & 7;
                int t2 = e >> 3;
                int px = t2 % HW, py = t2 / HW;
                int gy = y0 + py - 1, gx = x0 + px - 1;
                if (gy >= 0 && gy < r && gx >= 0 && gx < r) {
                    const float* pp = xin +
                        (((size_t)(b * NF + chunk * 16 + 2 * p)) * r + gy) * r + gx;
                    v0 = pp[0];
                    v1 = pp[rr];
                }
            }
            pv0[i] = v0;
            pv1[i] = v1;
        }
    };
    // ---- split + store prefetched x regs to smem
    auto store_x = [&]() {
        #pragma unroll
        for (int i = 0; i < MAXE; i++) {
            int e = t + i * 256;
            if (e < E) {
                int p = e & 7;
                int t2 = e >> 3;
                int px = t2 % HW, py = t2 / HW;
                unsigned int hi, lo;
                split2(pv0[i], pv1[i], hi, lo);
                int off = py * X_PYS + px * X_PXS + p;
                dyn[XH_OFF + off] = hi;
                dyn[XL_OFF + off] = lo;
            }
        }
    };

    // ---- prologue: chunk 0
    load_w(0, 0);
    cp_commit();
    fetch_x(0);
    store_x();
    cp_wait0();
    __syncthreads();

    #pragma unroll 1
    for (int chunk = 0; chunk < 8; chunk++) {
        if (chunk < 7) {
            load_w(chunk + 1, (chunk + 1) & 1);
            cp_commit();
            fetch_x(chunk + 1);
        }
        const unsigned int* wh = dyn + (chunk & 1) * W_BUF_U32;
        const unsigned int* wl = wh + NF * W_STRIDE;

        #pragma unroll 1
        for (int off = 0; off < 9; off++) {
            int ky = off / 3, kx = off - ky * 3;
            int wbase = (co_w + lq) * W_STRIDE + off * 8 + lr;
            unsigned int ah[4], al[4];
            ah[0] = wh[wbase];
            ah[1] = wh[wbase + 8 * W_STRIDE];
            ah[2] = wh[wbase + 4];
            ah[3] = wh[wbase + 8 * W_STRIDE + 4];
            al[0] = wl[wbase];
            al[1] = wl[wbase + 8 * W_STRIDE];
            al[2] = wl[wbase + 4];
            al[3] = wl[wbase + 8 * W_STRIDE + 4];
            int xbase = ky * X_PYS + (lq + kx) * X_PXS + lr;
            #pragma unroll
            for (int row = 0; row < 8; row++)
                #pragma unroll
                for (int cb = 0; cb < NCB; cb++) {
                    int xb = xbase + row * X_PYS + cb * (8 * X_PXS);
                    unsigned int bh[2], bl[2];
                    bh[0] = dyn[XH_OFF + xb];
                    bh[1] = dyn[XH_OFF + xb + 4];
                    bl[0] = dyn[XL_OFF + xb];
                    bl[1] = dyn[XL_OFF + xb + 4];
                    mma16816(acc[row][cb], ah, bh);
                    mma16816(acc[row][cb], ah, bl);
                    mma16816(acc[row][cb], al, bh);
                }
        }
        __syncthreads();
        if (chunk < 7) {
            store_x();
            cp_wait0();
            __syncthreads();
        }
    }

    // ---- epilogue: noise + bias + leaky relu
    float sn = __ldg(sn_ptr);
    int co0 = co_w + lq, co1 = co0 + 8;
    float bb0 = bias[co0], bb1 = bias[co1];
    float* op0 = xout + ((size_t)(b * NF + co0)) * rr;
    float* op1 = xout + ((size_t)(b * NF + co1)) * rr;
    #pragma unroll
    for (int row = 0; row < 8; row++)
        #pragma unroll
        for (int cb = 0; cb < NCB; cb++) {
            int gy = y0 + row;
            int gx = x0 + cb * 8 + 2 * lr;
            const float* np = noise + ((size_t)b * r + gy) * r + gx;
            float n0 = sn * np[0], n1 = sn * np[1];
            float u0 = acc[row][cb][0] + n0 + bb0;
            float u1 = acc[row][cb][1] + n1 + bb0;
            float u2 = acc[row][cb][2] + n0 + bb1;
            float u3 = acc[row][cb][3] + n1 + bb1;
            u0 = u0 > 0.f ? u0 : 0.2f * u0;
            u1 = u1 > 0.f ? u1 : 0.2f * u1;
            u2 = u2 > 0.f ? u2 : 0.2f * u2;
            u3 = u3 > 0.f ? u3 : 0.2f * u3;
            *reinterpret_cast<float2*>(op0 + (size_t)gy * r + gx) = make_float2(u0, u1);
            *reinterpret_cast<float2*>(op1 + (size_t)gy * r + gx) = make_float2(u2, u3);
        }
}

// ---------------- ToRGB ------------------------------------------------------
__global__ void k_rgb(const float* __restrict__ xin, float* __restrict__ rgbout,
                      const float* __restrict__ rgb_w, int i, int r) {
    int b = blockIdx.y;
    __shared__ float wr[NF];
    if (threadIdx.x < NF) {
        const float cr = 0.08838834764831843f;  // 1/sqrt(128)
        wr[threadIdx.x] = rgb_w[i * NF + threadIdx.x] * cr * g_s[(i * BSZ + b) * NF + threadIdx.x];
    }
    __syncthreads();
    int p = blockIdx.x * blockDim.x + threadIdx.x;
    if (p >= r * r) return;
    const float* xp = xin + (size_t)b * NF * r * r + p;
    float acc = 0.f;
    #pragma unroll 4
    for (int ci = 0; ci < NF; ci++) acc += wr[ci] * xp[(size_t)ci * r * r];
    rgbout[(size_t)b * r * r + p] = acc;
}

// ---------------- final ------------------------------------------------------
__global__ void k_final(float* __restrict__ out) {
    int idx = blockIdx.x * blockDim.x + threadIdx.x;
    if (idx >= BSZ * IMG * IMG) return;
    int b = idx / (IMG * IMG);
    int rem = idx - b * (IMG * IMG);
    int y = rem >> 8, x = rem & 255;
    float sum = 0.f;
    int roff = 0;
    #pragma unroll
    for (int i = 0; i < 4; i++) {
        int r = 32 << i;
        const float* src = g_rgb + (size_t)BSZ * roff + (size_t)b * r * r;
        float sc = (float)r * (1.f / 256.f);
        float fy = (y + 0.5f) * sc - 0.5f;
        float fx = (x + 0.5f) * sc - 0.5f;
        int iy0 = (int)floorf(fy), ix0 = (int)floorf(fx);
        float ty = fy - iy0, tx = fx - ix0;
        int y0c = max(iy0, 0), y1c = min(iy0 + 1, r - 1);
        int x0c = max(ix0, 0), x1c = min(ix0 + 1, r - 1);
        float v00 = src[y0c * r + x0c], v01 = src[y0c * r + x1c];
        float v10 = src[y1c * r + x0c], v11 = src[y1c * r + x1c];
        float v0 = v00 + tx * (v01 - v00);
        float v1 = v10 + tx * (v11 - v10);
        sum += v0 + ty * (v1 - v0);
        roff += r * r;
    }
    out[idx] = sum * 0.5f + 0.5f;
}

// =============================================================================
static inline int conv_smem_bytes(int TPX) {
    int hw = TPX + 2;
    int x_u32 = 2 * 10 * hw * X_PXS;
    return (W_TOTAL_U32 + x_u32) * 4;
}

extern "C" void kernel_launch(void* const* d_in, const int* in_sizes, int n_in,
                              void* d_out, int out_size) {
    const float* w      = (const float*)d_in[0];
    const float* noise_in[4] = { (const float*)d_in[1], (const float*)d_in[2],
                                 (const float*)d_in[3], (const float*)d_in[4] };
    const float* ic     = (const float*)d_in[5];
    const float* tsw    = (const float*)d_in[6];
    const float* tsb    = (const float*)d_in[7];
    const float* conv_w = (const float*)d_in[8];
    const float* sn     = (const float*)d_in[9];
    const float* sbias  = (const float*)d_in[10];
    const float* rgb_w  = (const float*)d_in[11];
    float* out = (float*)d_out;

    float *xa, *xb, *rgb;
    cudaGetSymbolAddress((void**)&xa, g_xa);
    cudaGetSymbolAddress((void**)&xb, g_xb);
    cudaGetSymbolAddress((void**)&rgb, g_rgb);

    const int smem8  = conv_smem_bytes(8);
    const int smem16 = conv_smem_bytes(16);
    cudaFuncSetAttribute(k_conv_mma<8>,
                         cudaFuncAttributeMaxDynamicSharedMemorySize, smem8);
    cudaFuncSetAttribute(k_conv_mma<16>,
                         cudaFuncAttributeMaxDynamicSharedMemorySize, smem16);

    k_style<<<NB * BSZ, 128>>>(w, tsw, tsb);

    {
        int n = BSZ * NF * 32 * 32;
        k_init<<<(n + 255) / 256, 256>>>(ic, xa);
    }

    float* cur = xa;
    float* tmp = xb;
    int rgboff = 0;
    for (int i = 0; i < NB; i++) {
        int r = 32 << i;
        if (i > 0) {
            int n = BSZ * NF * r * r;
            k_up<<<(n + 255) / 256, 256>>>(cur, tmp, r / 2);
            float* t2 = cur; cur = tmp; tmp = t2;
        }
        for (int j = 0; j < 2; j++) {
            k_modw<<<BSZ * NF, 256>>>(conv_w, i, j);
            const float* nz = noise_in[i] + (size_t)j * BSZ * r * r;
            const float* snp = sn + (i * 2 + j);
            const float* bp = sbias + (i * 2 + j) * NF;
            if (r == 32) {
                dim3 grid(r / 8, r / 8, BSZ);
                k_conv_mma<8><<<grid, 256, smem8>>>(cur, tmp, nz, snp, bp, r);
            } else {
                dim3 grid(r / 16, r / 8, BSZ);
                k_conv_mma<16><<<grid, 256, smem16>>>(cur, tmp, nz, snp, bp, r);
            }
            float* t2 = cur; cur = tmp; tmp = t2;
        }
        dim3 rg((r * r + 255) / 256, BSZ);
        k_rgb<<<rg, 256>>>(cur, rgb + (size_t)BSZ * rgboff, rgb_w, i, r);
        rgboff += r * r;
    }

    {
        int n = BSZ * IMG * IMG;
        k_final<<<(n + 255) / 256, 256>>>(out);
    }
}